// round 11
// baseline (speedup 1.0000x reference)
#include <cuda_runtime.h>

#define YD 384
#define XD 512
#define EPSR 1e-4f

typedef unsigned long long u64;

__device__ __forceinline__ u64 f2sub(u64 a, u64 b) {
    u64 r; asm("sub.rn.f32x2 %0,%1,%2;" : "=l"(r) : "l"(a), "l"(b)); return r;
}
__device__ __forceinline__ u64 f2mul(u64 a, u64 b) {
    u64 r; asm("mul.rn.f32x2 %0,%1,%2;" : "=l"(r) : "l"(a), "l"(b)); return r;
}
__device__ __forceinline__ u64 f2fma(u64 a, u64 b, u64 c) {
    u64 r; asm("fma.rn.f32x2 %0,%1,%2,%3;" : "=l"(r) : "l"(a), "l"(b), "l"(c)); return r;
}
__device__ __forceinline__ u64 pack2(float lo, float hi) {
    u64 r; asm("mov.b64 %0,{%1,%2};" : "=l"(r) : "f"(lo), "f"(hi)); return r;
}
__device__ __forceinline__ ulonglong2 lerp2(ulonglong2 a, ulonglong2 b, u64 w2) {
    ulonglong2 r;
    r.x = f2fma(w2, f2sub(b.x, a.x), a.x);
    r.y = f2fma(w2, f2sub(b.y, a.y), a.y);
    return r;
}
__device__ __forceinline__ float cost2(ulonglong2 f0, ulonglong2 v) {
    u64 d0 = f2sub(f0.x, v.x);
    u64 d1 = f2sub(f0.y, v.y);
    u64 acc = f2fma(d1, d1, f2mul(d0, d0));
    float lo, hi; asm("mov.b64 {%0,%1},%2;" : "=f"(lo), "=f"(hi) : "l"(acc));
    return lo + hi;
}

// single-pixel cost path (interior or exact clamped border) — fallback
__device__ __forceinline__ void pixel_costs(
    const ulonglong2* __restrict__ f1q,
    const float4 f0, int bx, int by, float wx, float wy, int s, float* c)
{
    const bool interior = (bx >= 1) && (bx <= XD - 3) && (by >= 1) && (by <= YD - 3);
    if (interior) {
        const u64 wx2 = pack2(wx, wx);
        const u64 wy2 = pack2(wy, wy);
        ulonglong2 f0p; f0p.x = pack2(f0.x, f0.y); f0p.y = pack2(f0.z, f0.w);
        const ulonglong2* rp = f1q + ((size_t)(by - 1) * XD + (bx - 1)) * 8 + s;
        ulonglong2 p0 = rp[0], p1 = rp[8], p2 = rp[16], p3 = rp[24];
        ulonglong2 hp0 = lerp2(p0, p1, wx2);
        ulonglong2 hp1 = lerp2(p1, p2, wx2);
        ulonglong2 hp2 = lerp2(p2, p3, wx2);
#pragma unroll
        for (int r = 1; r < 4; r++) {
            const ulonglong2* q = rp + r * (XD * 8);
            p0 = q[0]; p1 = q[8]; p2 = q[16]; p3 = q[24];
            ulonglong2 hc0 = lerp2(p0, p1, wx2);
            ulonglong2 hc1 = lerp2(p1, p2, wx2);
            ulonglong2 hc2 = lerp2(p2, p3, wx2);
            c[(r - 1) * 3 + 0] = cost2(f0p, lerp2(hp0, hc0, wy2));
            c[(r - 1) * 3 + 1] = cost2(f0p, lerp2(hp1, hc1, wy2));
            c[(r - 1) * 3 + 2] = cost2(f0p, lerp2(hp2, hc2, wy2));
            hp0 = hc0; hp1 = hc1; hp2 = hc2;
        }
    } else {
        const float4* f1v = (const float4*)f1q;
#pragma unroll 1
        for (int k = 0; k < 9; k++) {
            const int ox = k % 3 - 1, oy = k / 3 - 1;
            int x0 = min(max(bx + ox, 0), XD - 1);
            int x1 = min(x0 + 1, XD - 1);
            int y0 = min(max(by + oy, 0), YD - 1);
            int y1 = min(y0 + 1, YD - 1);
            float4 f00 = __ldg(f1v + ((size_t)y0 * XD + x0) * 8 + s);
            float4 f01 = __ldg(f1v + ((size_t)y0 * XD + x1) * 8 + s);
            float4 f10 = __ldg(f1v + ((size_t)y1 * XD + x0) * 8 + s);
            float4 f11 = __ldg(f1v + ((size_t)y1 * XD + x1) * 8 + s);
            float tx = f00.x + wx * (f01.x - f00.x);
            float ty = f00.y + wx * (f01.y - f00.y);
            float tz = f00.z + wx * (f01.z - f00.z);
            float tw = f00.w + wx * (f01.w - f00.w);
            float bxv = f10.x + wx * (f11.x - f10.x);
            float byv = f10.y + wx * (f11.y - f10.y);
            float bzv = f10.z + wx * (f11.z - f10.z);
            float bwv = f10.w + wx * (f11.w - f10.w);
            float vx = tx + wy * (bxv - tx);
            float vy = ty + wy * (byv - ty);
            float vz = tz + wy * (bzv - tz);
            float vw = tw + wy * (bwv - tw);
            float dx = f0.x - vx, dy = f0.y - vy, dz = f0.z - vz, dw = f0.w - vw;
            c[k] = dx * dx + dy * dy + dz * dz + dw * dw;
        }
    }
}

__global__ __launch_bounds__(256) void quadfit_kernel(
    const float* __restrict__ feat0,
    const float* __restrict__ feat1,
    const float* __restrict__ flow,
    float* __restrict__ out)
{
    __shared__ float c_s[256 * 9];
    const int w    = threadIdx.x >> 5;   // warp 0..7
    const int lane = threadIdx.x & 31;
    const int g    = lane >> 3;          // pixel group within warp 0..3
    const int s    = lane & 7;           // sublane = 16-byte channel slot 0..7
    const int base = blockIdx.x * 256;
    const unsigned gm = 0xFFu << (g * 8);   // 8-lane group mask (legal under group divergence)

    const float4*     __restrict__ f0v = (const float4*)feat0;
    const ulonglong2* __restrict__ f1q = (const ulonglong2*)feat1;

    // ---------------- Phase A: pairs of pixels per group per step (2x MLP) ----------------
#pragma unroll 1
    for (int it2 = 0; it2 < 4; ++it2) {
        const int liA = (it2 * 2) * 32 + w * 4 + g;
        const int liB = liA + 32;
        const int pA  = base + liA;
        const int pB  = base + liB;

        // head for BOTH pixels: loads issue together
        const float uA = __ldg(flow + pA * 3 + 0);
        const float vA = __ldg(flow + pA * 3 + 1);
        const float uB = __ldg(flow + pB * 3 + 0);
        const float vB = __ldg(flow + pB * 3 + 1);
        const float4 f0A = f0v[pA * 8 + s];
        const float4 f0B = f0v[pB * 8 + s];

        const float pxA = (float)(pA & 511) + uA;
        const float pyA = (float)(pA >> 9) + vA;
        const float pxB = (float)(pB & 511) + uB;
        const float pyB = (float)(pB >> 9) + vB;
        const float bxfA = floorf(pxA), byfA = floorf(pyA);
        const float bxfB = floorf(pxB), byfB = floorf(pyB);
        const float wxA = pxA - bxfA, wyA = pyA - byfA;
        const float wxB = pxB - bxfB, wyB = pyB - byfB;
        const int bxA = (int)bxfA, byA = (int)byfA;
        const int bxB = (int)bxfB, byB = (int)byfB;

        const bool intA = (bxA >= 1) && (bxA <= XD - 3) && (byA >= 1) && (byA <= YD - 3);
        const bool intB = (bxB >= 1) && (bxB <= XD - 3) && (byB >= 1) && (byB <= YD - 3);

        if (intA && intB) {
            // dual interleaved interior streams: 8 patch LDGs in flight per row step
            const u64 wxA2 = pack2(wxA, wxA), wyA2 = pack2(wyA, wyA);
            const u64 wxB2 = pack2(wxB, wxB), wyB2 = pack2(wyB, wyB);
            ulonglong2 fA; fA.x = pack2(f0A.x, f0A.y); fA.y = pack2(f0A.z, f0A.w);
            ulonglong2 fB; fB.x = pack2(f0B.x, f0B.y); fB.y = pack2(f0B.z, f0B.w);

            const ulonglong2* rpA = f1q + ((size_t)(byA - 1) * XD + (bxA - 1)) * 8 + s;
            const ulonglong2* rpB = f1q + ((size_t)(byB - 1) * XD + (bxB - 1)) * 8 + s;

            ulonglong2 a0 = rpA[0], a1 = rpA[8], a2 = rpA[16], a3 = rpA[24];
            ulonglong2 b0 = rpB[0], b1 = rpB[8], b2 = rpB[16], b3 = rpB[24];
            ulonglong2 hA0 = lerp2(a0, a1, wxA2);
            ulonglong2 hA1 = lerp2(a1, a2, wxA2);
            ulonglong2 hA2 = lerp2(a2, a3, wxA2);
            ulonglong2 hB0 = lerp2(b0, b1, wxB2);
            ulonglong2 hB1 = lerp2(b1, b2, wxB2);
            ulonglong2 hB2 = lerp2(b2, b3, wxB2);

#pragma unroll
            for (int r = 1; r < 4; r++) {
                const ulonglong2* qA = rpA + r * (XD * 8);
                const ulonglong2* qB = rpB + r * (XD * 8);
                a0 = qA[0]; a1 = qA[8]; a2 = qA[16]; a3 = qA[24];
                b0 = qB[0]; b1 = qB[8]; b2 = qB[16]; b3 = qB[24];
                ulonglong2 cA0 = lerp2(a0, a1, wxA2);
                ulonglong2 cA1 = lerp2(a1, a2, wxA2);
                ulonglong2 cA2 = lerp2(a2, a3, wxA2);
                ulonglong2 cB0 = lerp2(b0, b1, wxB2);
                ulonglong2 cB1 = lerp2(b1, b2, wxB2);
                ulonglong2 cB2 = lerp2(b2, b3, wxB2);
                float t0 = cost2(fA, lerp2(hA0, cA0, wyA2));
                float t1 = cost2(fA, lerp2(hA1, cA1, wyA2));
                float t2 = cost2(fA, lerp2(hA2, cA2, wyA2));
                float u0 = cost2(fB, lerp2(hB0, cB0, wyB2));
                float u1 = cost2(fB, lerp2(hB1, cB1, wyB2));
                float u2 = cost2(fB, lerp2(hB2, cB2, wyB2));
                // 6 independent 3-deep group-reductions; overlap with next row's loads
#pragma unroll
                for (int d = 4; d >= 1; d >>= 1) {
                    t0 += __shfl_xor_sync(gm, t0, d);
                    t1 += __shfl_xor_sync(gm, t1, d);
                    t2 += __shfl_xor_sync(gm, t2, d);
                    u0 += __shfl_xor_sync(gm, u0, d);
                    u1 += __shfl_xor_sync(gm, u1, d);
                    u2 += __shfl_xor_sync(gm, u2, d);
                }
                if (s == 0) {
                    c_s[liA * 9 + (r - 1) * 3 + 0] = t0;
                    c_s[liA * 9 + (r - 1) * 3 + 1] = t1;
                    c_s[liA * 9 + (r - 1) * 3 + 2] = t2;
                    c_s[liB * 9 + (r - 1) * 3 + 0] = u0;
                    c_s[liB * 9 + (r - 1) * 3 + 1] = u1;
                    c_s[liB * 9 + (r - 1) * 3 + 2] = u2;
                }
                hA0 = cA0; hA1 = cA1; hA2 = cA2;
                hB0 = cB0; hB1 = cB1; hB2 = cB2;
            }
        } else {
            // fallback: sequential single-pixel paths (rare)
            float c[9];
            pixel_costs(f1q, f0A, bxA, byA, wxA, wyA, s, c);
#pragma unroll
            for (int k = 0; k < 9; k++) {
                float vr = c[k];
                vr += __shfl_xor_sync(gm, vr, 4);
                vr += __shfl_xor_sync(gm, vr, 2);
                vr += __shfl_xor_sync(gm, vr, 1);
                if (s == 0) c_s[liA * 9 + k] = vr;
            }
            pixel_costs(f1q, f0B, bxB, byB, wxB, wyB, s, c);
#pragma unroll
            for (int k = 0; k < 9; k++) {
                float vr = c[k];
                vr += __shfl_xor_sync(gm, vr, 4);
                vr += __shfl_xor_sync(gm, vr, 2);
                vr += __shfl_xor_sync(gm, vr, 1);
                if (s == 0) c_s[liB * 9 + k] = vr;
            }
        }
    }

    __syncthreads();

    // ---------------- Phase B (lean): softmax + in-place Cholesky ----------------
    {
        const int t = threadIdx.x;
        const int p = base + t;

        float c[9];
#pragma unroll
        for (int k = 0; k < 9; k++) c[k] = c_s[t * 9 + k];

        float m = c[0];
#pragma unroll
        for (int k = 1; k < 9; k++) m = fminf(m, c[k]);
        float wgt[9];
        float sums = 0.f;
#pragma unroll
        for (int k = 0; k < 9; k++) { wgt[k] = __expf(m - c[k]); sums += wgt[k]; }
        const float inv_s = 1.f / sums;
#pragma unroll
        for (int k = 0; k < 9; k++) wgt[k] *= inv_s;

        float M[21];
        float r6[6];
#pragma unroll
        for (int i = 0; i < 21; i++) M[i] = 0.f;
#pragma unroll
        for (int i = 0; i < 6; i++) r6[i] = 0.f;
#pragma unroll
        for (int k = 0; k < 9; k++) {
            const float ox = (float)(k % 3 - 1);
            const float oy = (float)(k / 3 - 1);
            const float a[6] = {ox * ox, oy * oy, ox * oy, ox, oy, 1.f};
            const float wk = wgt[k];
            const float wc = wk * c[k];
            int idx = 0;
#pragma unroll
            for (int i = 0; i < 6; i++) {
                r6[i] += a[i] * wc;
#pragma unroll
                for (int j = 0; j <= i; j++) { M[idx] += a[i] * a[j] * wk; idx++; }
            }
        }
        M[0] += EPSR; M[2] += EPSR; M[5] += EPSR; M[9] += EPSR; M[14] += EPSR; M[20] += EPSR;

        float invd[6];
#pragma unroll
        for (int j = 0; j < 6; j++) {
            float d = M[j * (j + 1) / 2 + j];
#pragma unroll
            for (int k2 = 0; k2 < j; k2++) { float l = M[j * (j + 1) / 2 + k2]; d -= l * l; }
            const float iv = rsqrtf(d);
            invd[j] = iv;
            M[j * (j + 1) / 2 + j] = d * iv;
#pragma unroll
            for (int i = j + 1; i < 6; i++) {
                float sij = M[i * (i + 1) / 2 + j];
#pragma unroll
                for (int k2 = 0; k2 < j; k2++)
                    sij -= M[i * (i + 1) / 2 + k2] * M[j * (j + 1) / 2 + k2];
                M[i * (i + 1) / 2 + j] = sij * iv;
            }
        }

        float xv[6];
        {
            float yv[6];
#pragma unroll
            for (int i = 0; i < 6; i++) {
                float s2 = r6[i];
#pragma unroll
                for (int k2 = 0; k2 < i; k2++) s2 -= M[i * (i + 1) / 2 + k2] * yv[k2];
                yv[i] = s2 * invd[i];
            }
#pragma unroll
            for (int i = 5; i >= 0; i--) {
                float s2 = yv[i];
#pragma unroll
                for (int k2 = i + 1; k2 < 6; k2++) s2 -= M[k2 * (k2 + 1) / 2 + i] * xv[k2];
                xv[i] = s2 * invd[i];
            }
        }

        float2* op = reinterpret_cast<float2*>(out + (size_t)p * 6);
        op[0] = make_float2(xv[0], xv[1]);
        op[1] = make_float2(xv[2], xv[3]);
        op[2] = make_float2(xv[4], xv[5]);
    }
}

extern "C" void kernel_launch(void* const* d_in, const int* in_sizes, int n_in,
                              void* d_out, int out_size)
{
    const float* feat0 = (const float*)d_in[0];
    const float* feat1 = (const float*)d_in[1];
    const float* flow  = (const float*)d_in[2];
    float* out = (float*)d_out;
    quadfit_kernel<<<(YD * XD) / 256, 256>>>(feat0, feat1, flow, out);
}

// round 12
// speedup vs baseline: 1.7410x; 1.7410x over previous
#include <cuda_runtime.h>

#define YD 384
#define XD 512
#define EPSR 1e-4f

__global__ __launch_bounds__(256, 4) void quadfit_kernel(
    const float* __restrict__ feat0,
    const float* __restrict__ feat1,
    const float* __restrict__ flow,
    float* __restrict__ out)
{
    __shared__ float c_s[256 * 9];
    const int w    = threadIdx.x >> 5;   // warp 0..7
    const int lane = threadIdx.x & 31;
    const int g    = lane >> 3;          // pixel group within warp 0..3
    const int s    = lane & 7;           // sublane = float4 channel slot 0..7
    const int base = blockIdx.x * 256;

    const float4* __restrict__ f0v = (const float4*)feat0;
    const float4* __restrict__ f1v = (const float4*)feat1;

    // ---------------- Phase A (R2 verbatim): 4 pixels/warp, 8 lanes (float4)/pixel ----------------
#pragma unroll 1
    for (int it = 0; it < 8; ++it) {
        const int li  = it * 32 + w * 4 + g;  // local pixel in block
        const int p   = base + li;            // linear pixel
        const int pyi = p >> 9;               // X = 512
        const int pxi = p & 511;

        const float u = flow[p * 3 + 0];
        const float v = flow[p * 3 + 1];
        const float px = (float)pxi + u;
        const float py = (float)pyi + v;
        const float bxf = floorf(px), byf = floorf(py);
        const float wx = px - bxf, wy = py - byf;
        const int bx = (int)bxf, by = (int)byf;

        const float4 f0 = f0v[p * 8 + s];

        float c[9];
        const bool interior = (bx >= 1) && (bx <= XD - 3) && (by >= 1) && (by <= YD - 3);
        if (interior) {
            const float4* rp = f1v + ((size_t)(by - 1) * XD + (bx - 1)) * 8 + s;
            float4 hp0, hp1, hp2;   // previous row horizontal lerps
            {
                float4 p0 = __ldg(rp + 0);
                float4 p1 = __ldg(rp + 8);
                float4 p2 = __ldg(rp + 16);
                float4 p3 = __ldg(rp + 24);
                hp0.x = p0.x + wx * (p1.x - p0.x); hp0.y = p0.y + wx * (p1.y - p0.y);
                hp0.z = p0.z + wx * (p1.z - p0.z); hp0.w = p0.w + wx * (p1.w - p0.w);
                hp1.x = p1.x + wx * (p2.x - p1.x); hp1.y = p1.y + wx * (p2.y - p1.y);
                hp1.z = p1.z + wx * (p2.z - p1.z); hp1.w = p1.w + wx * (p2.w - p1.w);
                hp2.x = p2.x + wx * (p3.x - p2.x); hp2.y = p2.y + wx * (p3.y - p2.y);
                hp2.z = p2.z + wx * (p3.z - p2.z); hp2.w = p2.w + wx * (p3.w - p2.w);
            }
#pragma unroll
            for (int r = 1; r < 4; r++) {
                const float4* q = rp + r * (XD * 8);
                float4 p0 = __ldg(q + 0);
                float4 p1 = __ldg(q + 8);
                float4 p2 = __ldg(q + 16);
                float4 p3 = __ldg(q + 24);
                float4 hc0, hc1, hc2;
                hc0.x = p0.x + wx * (p1.x - p0.x); hc0.y = p0.y + wx * (p1.y - p0.y);
                hc0.z = p0.z + wx * (p1.z - p0.z); hc0.w = p0.w + wx * (p1.w - p0.w);
                hc1.x = p1.x + wx * (p2.x - p1.x); hc1.y = p1.y + wx * (p2.y - p1.y);
                hc1.z = p1.z + wx * (p2.z - p1.z); hc1.w = p1.w + wx * (p2.w - p1.w);
                hc2.x = p2.x + wx * (p3.x - p2.x); hc2.y = p2.y + wx * (p3.y - p2.y);
                hc2.z = p2.z + wx * (p3.z - p2.z); hc2.w = p2.w + wx * (p3.w - p2.w);
#pragma unroll
                for (int cc = 0; cc < 3; cc++) {
                    const float4 hp = (cc == 0) ? hp0 : (cc == 1) ? hp1 : hp2;
                    const float4 hc = (cc == 0) ? hc0 : (cc == 1) ? hc1 : hc2;
                    float vx = hp.x + wy * (hc.x - hp.x);
                    float vy = hp.y + wy * (hc.y - hp.y);
                    float vz = hp.z + wy * (hc.z - hp.z);
                    float vw = hp.w + wy * (hc.w - hp.w);
                    float dx = f0.x - vx, dy = f0.y - vy, dz = f0.z - vz, dw = f0.w - vw;
                    c[(r - 1) * 3 + cc] = dx * dx + dy * dy + dz * dz + dw * dw;
                }
                hp0 = hc0; hp1 = hc1; hp2 = hc2;
            }
        } else {
            // exact clamped path (matches reference: x1 = clip(clip(x0)+1))
#pragma unroll 1
            for (int k = 0; k < 9; k++) {
                const int ox = k % 3 - 1, oy = k / 3 - 1;
                int x0 = min(max(bx + ox, 0), XD - 1);
                int x1 = min(x0 + 1, XD - 1);
                int y0 = min(max(by + oy, 0), YD - 1);
                int y1 = min(y0 + 1, YD - 1);
                float4 f00 = __ldg(f1v + ((size_t)y0 * XD + x0) * 8 + s);
                float4 f01 = __ldg(f1v + ((size_t)y0 * XD + x1) * 8 + s);
                float4 f10 = __ldg(f1v + ((size_t)y1 * XD + x0) * 8 + s);
                float4 f11 = __ldg(f1v + ((size_t)y1 * XD + x1) * 8 + s);
                float tx = f00.x + wx * (f01.x - f00.x);
                float ty = f00.y + wx * (f01.y - f00.y);
                float tz = f00.z + wx * (f01.z - f00.z);
                float tw = f00.w + wx * (f01.w - f00.w);
                float bxv = f10.x + wx * (f11.x - f10.x);
                float byv = f10.y + wx * (f11.y - f10.y);
                float bzv = f10.z + wx * (f11.z - f10.z);
                float bwv = f10.w + wx * (f11.w - f10.w);
                float vx = tx + wy * (bxv - tx);
                float vy = ty + wy * (byv - ty);
                float vz = tz + wy * (bzv - tz);
                float vw = tw + wy * (bwv - tw);
                float dx = f0.x - vx, dy = f0.y - vy, dz = f0.z - vz, dw = f0.w - vw;
                c[k] = dx * dx + dy * dy + dz * dz + dw * dw;
            }
        }

        // batch butterfly reduce (9 independent 3-deep chains — full ILP)
#pragma unroll
        for (int k = 0; k < 9; k++) {
            float vr = c[k];
            vr += __shfl_xor_sync(0xffffffffu, vr, 4);
            vr += __shfl_xor_sync(0xffffffffu, vr, 2);
            vr += __shfl_xor_sync(0xffffffffu, vr, 1);
            c[k] = vr;
        }
        if (s == 0) {
#pragma unroll
            for (int k = 0; k < 9; k++) c_s[li * 9 + k] = c[k];
        }
    }

    __syncthreads();

    // ---------------- Phase B: moment-compressed softmax-weighted 6x6 solve ----------------
    {
        const int t = threadIdx.x;
        const int p = base + t;

        // pass 0: min cost (softmax stabilizer)
        float m = c_s[t * 9 + 0];
#pragma unroll
        for (int k = 1; k < 9; k++) m = fminf(m, c_s[t * 9 + k]);

        // pass 1: normalizer
        float sums = 0.f;
#pragma unroll
        for (int k = 0; k < 9; k++) sums += __expf(m - c_s[t * 9 + k]);
        const float inv_s = 1.f / sums;

        // pass 2: accumulate 9 moments + 6 rhs (coefficients are 0/±1 -> folded adds).
        // Each accumulator sums the SAME terms in the SAME k-order as the old
        // 21-entry AtWA build -> bit-identical values.
        float S = 0.f, Sx = 0.f, Sy = 0.f, Sxx = 0.f, Syy = 0.f, Sxy = 0.f;
        float Sxxy = 0.f, Sxyy = 0.f, Sxxyy = 0.f;
        float r0 = 0.f, r1 = 0.f, r2 = 0.f, r3 = 0.f, r4 = 0.f, r5 = 0.f;
#pragma unroll
        for (int k = 0; k < 9; k++) {
            const float fx = (float)(k % 3 - 1);
            const float fy = (float)(k / 3 - 1);
            const float ck = c_s[t * 9 + k];
            const float wk = __expf(m - ck) * inv_s;
            const float wc = wk * ck;
            S     += wk;
            Sx    += fx * wk;
            Sy    += fy * wk;
            Sxx   += fx * fx * wk;
            Syy   += fy * fy * wk;
            Sxy   += fx * fy * wk;
            Sxxy  += fx * fx * fy * wk;
            Sxyy  += fx * fy * fy * wk;
            Sxxyy += fx * fx * fy * fy * wk;
            r0 += fx * fx * wc;
            r1 += fy * fy * wc;
            r2 += fx * fy * wc;
            r3 += fx * wc;
            r4 += fy * wc;
            r5 += wc;
        }

        // materialize AtWA + EPS*I (lower triangle, idx(i,j)=i*(i+1)/2+j)
        // using ox^3=ox, ox^4=ox^2 identities; unknown order (x^2,y^2,xy,x,y,1)
        float L[21];
        L[0]  = Sxx + EPSR;
        L[1]  = Sxxyy;  L[2]  = Syy + EPSR;
        L[3]  = Sxy;    L[4]  = Sxy;    L[5]  = Sxxyy + EPSR;
        L[6]  = Sx;     L[7]  = Sxyy;   L[8]  = Sxxy;   L[9]  = Sxx + EPSR;
        L[10] = Sxxy;   L[11] = Sy;     L[12] = Sxyy;   L[13] = Sxy;  L[14] = Syy + EPSR;
        L[15] = Sxx;    L[16] = Syy;    L[17] = Sxy;    L[18] = Sx;   L[19] = Sy;  L[20] = S + EPSR;

        float r6[6] = {r0, r1, r2, r3, r4, r5};

        // in-place Cholesky: L becomes the factor
        float invd[6];
#pragma unroll
        for (int j = 0; j < 6; j++) {
            float d = L[j * (j + 1) / 2 + j];
#pragma unroll
            for (int k2 = 0; k2 < j; k2++) { float l = L[j * (j + 1) / 2 + k2]; d -= l * l; }
            const float iv = rsqrtf(d);
            invd[j] = iv;
            L[j * (j + 1) / 2 + j] = d * iv;
#pragma unroll
            for (int i = j + 1; i < 6; i++) {
                float sij = L[i * (i + 1) / 2 + j];
#pragma unroll
                for (int k2 = 0; k2 < j; k2++)
                    sij -= L[i * (i + 1) / 2 + k2] * L[j * (j + 1) / 2 + k2];
                L[i * (i + 1) / 2 + j] = sij * iv;
            }
        }

        // L y = rhs ; L^T x = y
        float xv[6];
        {
            float yv[6];
#pragma unroll
            for (int i = 0; i < 6; i++) {
                float s2 = r6[i];
#pragma unroll
                for (int k2 = 0; k2 < i; k2++) s2 -= L[i * (i + 1) / 2 + k2] * yv[k2];
                yv[i] = s2 * invd[i];
            }
#pragma unroll
            for (int i = 5; i >= 0; i--) {
                float s2 = yv[i];
#pragma unroll
                for (int k2 = i + 1; k2 < 6; k2++) s2 -= L[k2 * (k2 + 1) / 2 + i] * xv[k2];
                xv[i] = s2 * invd[i];
            }
        }

        float2* op = reinterpret_cast<float2*>(out + (size_t)p * 6);
        op[0] = make_float2(xv[0], xv[1]);
        op[1] = make_float2(xv[2], xv[3]);
        op[2] = make_float2(xv[4], xv[5]);
    }
}

extern "C" void kernel_launch(void* const* d_in, const int* in_sizes, int n_in,
                              void* d_out, int out_size)
{
    const float* feat0 = (const float*)d_in[0];
    const float* feat1 = (const float*)d_in[1];
    const float* flow  = (const float*)d_in[2];
    float* out = (float*)d_out;
    quadfit_kernel<<<(YD * XD) / 256, 256>>>(feat0, feat1, flow, out);
}

// round 15
// speedup vs baseline: 1.8555x; 1.0658x over previous
#include <cuda_runtime.h>

#define YD 384
#define XD 512
#define EPSR 1e-4f

__global__ __launch_bounds__(256) void quadfit_kernel(
    const float* __restrict__ feat0,
    const float* __restrict__ feat1,
    const float* __restrict__ flow,
    float* __restrict__ out)
{
    __shared__ float c_s[256 * 9];
    const int w    = threadIdx.x >> 5;   // warp 0..7
    const int lane = threadIdx.x & 31;
    const int g    = lane >> 3;          // pixel group within warp 0..3
    const int s    = lane & 7;           // sublane = float4 channel slot 0..7
    const int base = blockIdx.x * 256;

    const float4* __restrict__ f0v = (const float4*)feat0;
    const float4* __restrict__ f1v = (const float4*)feat1;

    // ---------------- Phase A (R2 verbatim): 4 pixels/warp, 8 lanes (float4)/pixel ----------------
#pragma unroll 1
    for (int it = 0; it < 8; ++it) {
        const int li  = it * 32 + w * 4 + g;  // local pixel in block
        const int p   = base + li;            // linear pixel
        const int pyi = p >> 9;               // X = 512
        const int pxi = p & 511;

        const float u = flow[p * 3 + 0];
        const float v = flow[p * 3 + 1];
        const float px = (float)pxi + u;
        const float py = (float)pyi + v;
        const float bxf = floorf(px), byf = floorf(py);
        const float wx = px - bxf, wy = py - byf;
        const int bx = (int)bxf, by = (int)byf;

        const float4 f0 = f0v[p * 8 + s];

        float c[9];
        const bool interior = (bx >= 1) && (bx <= XD - 3) && (by >= 1) && (by <= YD - 3);
        if (interior) {
            const float4* rp = f1v + ((size_t)(by - 1) * XD + (bx - 1)) * 8 + s;
            float4 hp0, hp1, hp2;   // previous row horizontal lerps
            {
                float4 p0 = __ldg(rp + 0);
                float4 p1 = __ldg(rp + 8);
                float4 p2 = __ldg(rp + 16);
                float4 p3 = __ldg(rp + 24);
                hp0.x = p0.x + wx * (p1.x - p0.x); hp0.y = p0.y + wx * (p1.y - p0.y);
                hp0.z = p0.z + wx * (p1.z - p0.z); hp0.w = p0.w + wx * (p1.w - p0.w);
                hp1.x = p1.x + wx * (p2.x - p1.x); hp1.y = p1.y + wx * (p2.y - p1.y);
                hp1.z = p1.z + wx * (p2.z - p1.z); hp1.w = p1.w + wx * (p2.w - p1.w);
                hp2.x = p2.x + wx * (p3.x - p2.x); hp2.y = p2.y + wx * (p3.y - p2.y);
                hp2.z = p2.z + wx * (p3.z - p2.z); hp2.w = p2.w + wx * (p3.w - p2.w);
            }
#pragma unroll
            for (int r = 1; r < 4; r++) {
                const float4* q = rp + r * (XD * 8);
                float4 p0 = __ldg(q + 0);
                float4 p1 = __ldg(q + 8);
                float4 p2 = __ldg(q + 16);
                float4 p3 = __ldg(q + 24);
                float4 hc0, hc1, hc2;
                hc0.x = p0.x + wx * (p1.x - p0.x); hc0.y = p0.y + wx * (p1.y - p0.y);
                hc0.z = p0.z + wx * (p1.z - p0.z); hc0.w = p0.w + wx * (p1.w - p0.w);
                hc1.x = p1.x + wx * (p2.x - p1.x); hc1.y = p1.y + wx * (p2.y - p1.y);
                hc1.z = p1.z + wx * (p2.z - p1.z); hc1.w = p1.w + wx * (p2.w - p1.w);
                hc2.x = p2.x + wx * (p3.x - p2.x); hc2.y = p2.y + wx * (p3.y - p2.y);
                hc2.z = p2.z + wx * (p3.z - p2.z); hc2.w = p2.w + wx * (p3.w - p2.w);
#pragma unroll
                for (int cc = 0; cc < 3; cc++) {
                    const float4 hp = (cc == 0) ? hp0 : (cc == 1) ? hp1 : hp2;
                    const float4 hc = (cc == 0) ? hc0 : (cc == 1) ? hc1 : hc2;
                    float vx = hp.x + wy * (hc.x - hp.x);
                    float vy = hp.y + wy * (hc.y - hp.y);
                    float vz = hp.z + wy * (hc.z - hp.z);
                    float vw = hp.w + wy * (hc.w - hp.w);
                    float dx = f0.x - vx, dy = f0.y - vy, dz = f0.z - vz, dw = f0.w - vw;
                    c[(r - 1) * 3 + cc] = dx * dx + dy * dy + dz * dz + dw * dw;
                }
                hp0 = hc0; hp1 = hc1; hp2 = hc2;
            }
        } else {
            // exact clamped path (matches reference: x1 = clip(clip(x0)+1))
#pragma unroll 1
            for (int k = 0; k < 9; k++) {
                const int ox = k % 3 - 1, oy = k / 3 - 1;
                int x0 = min(max(bx + ox, 0), XD - 1);
                int x1 = min(x0 + 1, XD - 1);
                int y0 = min(max(by + oy, 0), YD - 1);
                int y1 = min(y0 + 1, YD - 1);
                float4 f00 = __ldg(f1v + ((size_t)y0 * XD + x0) * 8 + s);
                float4 f01 = __ldg(f1v + ((size_t)y0 * XD + x1) * 8 + s);
                float4 f10 = __ldg(f1v + ((size_t)y1 * XD + x0) * 8 + s);
                float4 f11 = __ldg(f1v + ((size_t)y1 * XD + x1) * 8 + s);
                float tx = f00.x + wx * (f01.x - f00.x);
                float ty = f00.y + wx * (f01.y - f00.y);
                float tz = f00.z + wx * (f01.z - f00.z);
                float tw = f00.w + wx * (f01.w - f00.w);
                float bxv = f10.x + wx * (f11.x - f10.x);
                float byv = f10.y + wx * (f11.y - f10.y);
                float bzv = f10.z + wx * (f11.z - f10.z);
                float bwv = f10.w + wx * (f11.w - f10.w);
                float vx = tx + wy * (bxv - tx);
                float vy = ty + wy * (byv - ty);
                float vz = tz + wy * (bzv - tz);
                float vw = tw + wy * (bwv - tw);
                float dx = f0.x - vx, dy = f0.y - vy, dz = f0.z - vz, dw = f0.w - vw;
                c[k] = dx * dx + dy * dy + dz * dz + dw * dw;
            }
        }

        // batch butterfly reduce (9 independent 3-deep chains — full ILP)
#pragma unroll
        for (int k = 0; k < 9; k++) {
            float vr = c[k];
            vr += __shfl_xor_sync(0xffffffffu, vr, 4);
            vr += __shfl_xor_sync(0xffffffffu, vr, 2);
            vr += __shfl_xor_sync(0xffffffffu, vr, 1);
            c[k] = vr;
        }
        if (s == 0) {
#pragma unroll
            for (int k = 0; k < 9; k++) c_s[li * 9 + k] = c[k];
        }
    }

    __syncthreads();

    // ---------------- Phase B: moment-compressed softmax-weighted 6x6 solve ----------------
    {
        const int t = threadIdx.x;
        const int p = base + t;

        // pass 0: min cost (softmax stabilizer)
        float m = c_s[t * 9 + 0];
#pragma unroll
        for (int k = 1; k < 9; k++) m = fminf(m, c_s[t * 9 + k]);

        // pass 1: normalizer
        float sums = 0.f;
#pragma unroll
        for (int k = 0; k < 9; k++) sums += __expf(m - c_s[t * 9 + k]);
        const float inv_s = 1.f / sums;

        // pass 2: accumulate 9 moments + 6 rhs (coefficients are 0/±1 -> folded adds).
        float S = 0.f, Sx = 0.f, Sy = 0.f, Sxx = 0.f, Syy = 0.f, Sxy = 0.f;
        float Sxxy = 0.f, Sxyy = 0.f, Sxxyy = 0.f;
        float r0 = 0.f, r1 = 0.f, r2 = 0.f, r3 = 0.f, r4 = 0.f, r5 = 0.f;
#pragma unroll
        for (int k = 0; k < 9; k++) {
            const float fx = (float)(k % 3 - 1);
            const float fy = (float)(k / 3 - 1);
            const float ck = c_s[t * 9 + k];
            const float wk = __expf(m - ck) * inv_s;
            const float wc = wk * ck;
            S     += wk;
            Sx    += fx * wk;
            Sy    += fy * wk;
            Sxx   += fx * fx * wk;
            Syy   += fy * fy * wk;
            Sxy   += fx * fy * wk;
            Sxxy  += fx * fx * fy * wk;
            Sxyy  += fx * fy * fy * wk;
            Sxxyy += fx * fx * fy * fy * wk;
            r0 += fx * fx * wc;
            r1 += fy * fy * wc;
            r2 += fx * fy * wc;
            r3 += fx * wc;
            r4 += fy * wc;
            r5 += wc;
        }

        // materialize AtWA + EPS*I (lower triangle, idx(i,j)=i*(i+1)/2+j)
        float L[21];
        L[0]  = Sxx + EPSR;
        L[1]  = Sxxyy;  L[2]  = Syy + EPSR;
        L[3]  = Sxy;    L[4]  = Sxy;    L[5]  = Sxxyy + EPSR;
        L[6]  = Sx;     L[7]  = Sxyy;   L[8]  = Sxxy;   L[9]  = Sxx + EPSR;
        L[10] = Sxxy;   L[11] = Sy;     L[12] = Sxyy;   L[13] = Sxy;  L[14] = Syy + EPSR;
        L[15] = Sxx;    L[16] = Syy;    L[17] = Sxy;    L[18] = Sx;   L[19] = Sy;  L[20] = S + EPSR;

        float r6[6] = {r0, r1, r2, r3, r4, r5};

        // in-place Cholesky
        float invd[6];
#pragma unroll
        for (int j = 0; j < 6; j++) {
            float d = L[j * (j + 1) / 2 + j];
#pragma unroll
            for (int k2 = 0; k2 < j; k2++) { float l = L[j * (j + 1) / 2 + k2]; d -= l * l; }
            const float iv = rsqrtf(d);
            invd[j] = iv;
            L[j * (j + 1) / 2 + j] = d * iv;
#pragma unroll
            for (int i = j + 1; i < 6; i++) {
                float sij = L[i * (i + 1) / 2 + j];
#pragma unroll
                for (int k2 = 0; k2 < j; k2++)
                    sij -= L[i * (i + 1) / 2 + k2] * L[j * (j + 1) / 2 + k2];
                L[i * (i + 1) / 2 + j] = sij * iv;
            }
        }

        // L y = rhs ; L^T x = y
        float xv[6];
        {
            float yv[6];
#pragma unroll
            for (int i = 0; i < 6; i++) {
                float s2 = r6[i];
#pragma unroll
                for (int k2 = 0; k2 < i; k2++) s2 -= L[i * (i + 1) / 2 + k2] * yv[k2];
                yv[i] = s2 * invd[i];
            }
#pragma unroll
            for (int i = 5; i >= 0; i--) {
                float s2 = yv[i];
#pragma unroll
                for (int k2 = i + 1; k2 < 6; k2++) s2 -= L[k2 * (k2 + 1) / 2 + i] * xv[k2];
                xv[i] = s2 * invd[i];
            }
        }

        float2* op = reinterpret_cast<float2*>(out + (size_t)p * 6);
        op[0] = make_float2(xv[0], xv[1]);
        op[1] = make_float2(xv[2], xv[3]);
        op[2] = make_float2(xv[4], xv[5]);
    }
}

extern "C" void kernel_launch(void* const* d_in, const int* in_sizes, int n_in,
                              void* d_out, int out_size)
{
    const float* feat0 = (const float*)d_in[0];
    const float* feat1 = (const float*)d_in[1];
    const float* flow  = (const float*)d_in[2];
    float* out = (float*)d_out;
    quadfit_kernel<<<(YD * XD) / 256, 256>>>(feat0, feat1, flow, out);
}